// round 17
// baseline (speedup 1.0000x reference)
#include <cuda_runtime.h>
#include <math.h>

// Problem constants
#define NB 64
#define CC 384
#define LL 3136      // 56*56
#define MM 16
#define DD 384
#define L4 784       // LL/4 (float4 per lf row)

// scores tiling
#define LT   224     // l per scores CTA
#define NLB  14      // 3136/224
#define QP   388     // q_s row pitch (conflict-free a-frags)
#define LFP  232     // lf_s row pitch in scores (conflict-free b-frags)

// fusion tiling
#define FCH  112     // l per fusion chunk
#define NCH  28      // 3136/112
#define FP   116     // smem pitch in fusion (conflict-free a/b frags)

// Scratch (static device memory — no allocations)
__device__ float g_q[NB*MM*CC];        // scaled q, [n][m][c]
__device__ float g_p[NB*MM*LL];        // exp(scores), [n][m][l]
__device__ float g_spart[NLB*NB*MM];   // per-lblock exp sums
__device__ float g_f[NB*MM*CC];        // normalized fusion, [n][m][c]

#define CVT_TF32(o, i) asm("cvt.rna.tf32.f32 %0, %1;" : "=f"(o) : "f"(i))

__device__ __forceinline__ void mma_tf32(float& d0, float& d1, float& d2, float& d3,
                                         unsigned a0, unsigned a1, unsigned a2, unsigned a3,
                                         unsigned b0, unsigned b1) {
    asm("mma.sync.aligned.m16n8k8.row.col.f32.tf32.tf32.f32 "
        "{%0,%1,%2,%3}, {%4,%5,%6,%7}, {%8,%9}, {%0,%1,%2,%3};"
        : "+f"(d0), "+f"(d1), "+f"(d2), "+f"(d3)
        : "r"(a0), "r"(a1), "r"(a2), "r"(a3), "r"(b0), "r"(b1));
}

// ---------------------------------------------------------------------------
// Kernel 0: q[n,m,c] = scale * (sum_d x[n,m,d]*Wq[c,d] + bq[c])
// ---------------------------------------------------------------------------
__global__ __launch_bounds__(128) void k_q(const float* __restrict__ x,
                                           const float* __restrict__ Wq,
                                           const float* __restrict__ bq) {
    const int n = blockIdx.y;
    const int c = blockIdx.x * 128 + threadIdx.x;

    __shared__ float x_s[MM*DD];
    for (int j = threadIdx.x; j < MM*DD; j += 128) x_s[j] = x[n*MM*DD + j];
    __syncthreads();

    const float4* xs4  = reinterpret_cast<const float4*>(x_s);
    const float4* wrow = reinterpret_cast<const float4*>(Wq + (size_t)c*DD);

    float acc[MM];
    #pragma unroll
    for (int m = 0; m < MM; ++m) acc[m] = 0.f;

    #pragma unroll 2
    for (int d4 = 0; d4 < DD/4; ++d4) {
        const float4 w = wrow[d4];
        #pragma unroll
        for (int m = 0; m < MM; ++m) {
            const float4 xv = xs4[m*(DD/4) + d4];
            acc[m] += w.x*xv.x + w.y*xv.y + w.z*xv.z + w.w*xv.w;
        }
    }

    const float scale = 0.05103103630798287f;   // 384^-0.5
    const float b = bq[c];
    #pragma unroll
    for (int m = 0; m < MM; ++m)
        g_q[n*MM*CC + m*CC + c] = scale * (acc[m] + b);
}

// ---------------------------------------------------------------------------
// Kernel A (tensor): scores + exp + partial row sums.
// grid (NLB=14, 64), 224 threads (7 warps, warp = 32 l = 4 n-tiles of 8).
// D[16, 8] tf32 MMA, K over 384 c in 12 smem-staged blocks of 32.
// Epilogue: p = exp(score) -> g_p (float2 stores), partial sums -> g_spart.
// ---------------------------------------------------------------------------
__global__ __launch_bounds__(224) void k_scores(const float* __restrict__ lf) {
    extern __shared__ float sm[];
    float* q_s  = sm;                       // [16][QP]
    float* lf_s = sm + 16*QP;               // [32][LFP]
    float* red  = sm + 16*QP + 32*LFP;      // [7][16]

    const int n    = blockIdx.y;
    const int lb   = blockIdx.x;
    const int tid  = threadIdx.x;
    const int warp = tid >> 5;
    const int tg   = tid & 3;               // threadID in group (k index)
    const int gid  = (tid & 31) >> 2;       // group id (m / n index)

    // stage q with tf32 rounding
    for (int j = tid; j < MM*CC; j += 224) {
        const int m = j / CC, c = j % CC;
        float t; CVT_TF32(t, g_q[n*MM*CC + j]);
        q_s[m*QP + c] = t;
    }

    float d[4][4];
    #pragma unroll
    for (int t = 0; t < 4; ++t) { d[t][0]=0.f; d[t][1]=0.f; d[t][2]=0.f; d[t][3]=0.f; }

    const float4* lfg = reinterpret_cast<const float4*>(lf)
                        + (size_t)n*CC*L4 + lb*(LT/4);

    for (int cb = 0; cb < 12; ++cb) {
        __syncthreads();
        // stage lf rows c = cb*32..+31, 224 cols (56 float4 per row)
        for (int j = tid; j < 32*56; j += 224) {
            const int r = j / 56, c4 = j % 56;
            const float4 v = lfg[(size_t)(cb*32 + r)*L4 + c4];
            float4 t;
            CVT_TF32(t.x, v.x); CVT_TF32(t.y, v.y);
            CVT_TF32(t.z, v.z); CVT_TF32(t.w, v.w);
            *reinterpret_cast<float4*>(&lf_s[r*LFP + c4*4]) = t;
        }
        __syncthreads();

        #pragma unroll
        for (int kk = 0; kk < 4; ++kk) {
            const int cg = cb*32 + kk*8;   // global c base for this k-step
            const unsigned a0 = __float_as_uint(q_s[ gid     *QP + cg + tg    ]);
            const unsigned a1 = __float_as_uint(q_s[(gid + 8)*QP + cg + tg    ]);
            const unsigned a2 = __float_as_uint(q_s[ gid     *QP + cg + tg + 4]);
            const unsigned a3 = __float_as_uint(q_s[(gid + 8)*QP + cg + tg + 4]);
            #pragma unroll
            for (int t = 0; t < 4; ++t) {
                const int lcol = warp*32 + t*8 + gid;
                const unsigned b0 = __float_as_uint(lf_s[(kk*8 + tg    )*LFP + lcol]);
                const unsigned b1 = __float_as_uint(lf_s[(kk*8 + tg + 4)*LFP + lcol]);
                mma_tf32(d[t][0], d[t][1], d[t][2], d[t][3], a0, a1, a2, a3, b0, b1);
            }
        }
    }

    // epilogue: exp, coalesced-ish float2 stores, partial sums
    float sum_lo = 0.f, sum_hi = 0.f;
    float* prow_lo = g_p + ((size_t)n*MM + gid    )*LL;
    float* prow_hi = g_p + ((size_t)n*MM + gid + 8)*LL;
    #pragma unroll
    for (int t = 0; t < 4; ++t) {
        const int l = lb*LT + warp*32 + t*8 + 2*tg;
        const float e0 = __expf(d[t][0]), e1 = __expf(d[t][1]);
        const float e2 = __expf(d[t][2]), e3 = __expf(d[t][3]);
        *reinterpret_cast<float2*>(prow_lo + l) = make_float2(e0, e1);
        *reinterpret_cast<float2*>(prow_hi + l) = make_float2(e2, e3);
        sum_lo += e0 + e1;
        sum_hi += e2 + e3;
    }
    // reduce over the 4 lanes of each group (lanes differ only in low 2 bits)
    sum_lo += __shfl_xor_sync(0xffffffffu, sum_lo, 1);
    sum_lo += __shfl_xor_sync(0xffffffffu, sum_lo, 2);
    sum_hi += __shfl_xor_sync(0xffffffffu, sum_hi, 1);
    sum_hi += __shfl_xor_sync(0xffffffffu, sum_hi, 2);
    if (tg == 0) {
        red[warp*16 + gid    ] = sum_lo;
        red[warp*16 + gid + 8] = sum_hi;
    }
    __syncthreads();
    if (tid < 16) {
        float s = 0.f;
        #pragma unroll
        for (int w = 0; w < 7; ++w) s += red[w*16 + tid];
        g_spart[(lb*NB + n)*MM + tid] = s;
    }
}

// ---------------------------------------------------------------------------
// Kernel C (tensor): f[n,m,c] = (1/sum) * sum_l p[m,l] * lf[c,l]
// grid (6, 64) = 384 CTAs (single wave), 256 threads; warp owns one 8-c tile.
// 28 chunks of 112 l staged in smem; D accumulates over all 3136 l in regs.
// ---------------------------------------------------------------------------
__global__ __launch_bounds__(256) void k_fusion(const float* __restrict__ lf) {
    __shared__ float lf_s[64*FP];
    __shared__ float p_s[16*FP];
    __shared__ float inv_s[MM];

    const int n    = blockIdx.y;
    const int cblk = blockIdx.x;            // 6 blocks of 64 c
    const int tid  = threadIdx.x;
    const int warp = tid >> 5;
    const int tg   = tid & 3;
    const int gid  = (tid & 31) >> 2;

    if (tid < MM) {
        float s = 0.f;
        #pragma unroll
        for (int lb = 0; lb < NLB; ++lb) s += g_spart[(lb*NB + n)*MM + tid];
        inv_s[tid] = 1.0f / s;
    }

    float d0 = 0.f, d1 = 0.f, d2 = 0.f, d3 = 0.f;

    const float4* lfg = reinterpret_cast<const float4*>(lf) + (size_t)n*CC*L4;
    const float4* pg  = reinterpret_cast<const float4*>(g_p) + (size_t)n*MM*L4;

    for (int ch = 0; ch < NCH; ++ch) {
        __syncthreads();
        // stage lf: 64 rows (c) x 28 float4 = 1792
        #pragma unroll
        for (int k = 0; k < 7; ++k) {
            const int j = tid + k*256;
            const int r = j / 28, c4 = j % 28;
            const float4 v = lfg[(size_t)(cblk*64 + r)*L4 + ch*28 + c4];
            float4 t;
            CVT_TF32(t.x, v.x); CVT_TF32(t.y, v.y);
            CVT_TF32(t.z, v.z); CVT_TF32(t.w, v.w);
            *reinterpret_cast<float4*>(&lf_s[r*FP + c4*4]) = t;
        }
        // stage p: 16 rows (m) x 28 float4 = 448
        for (int j = tid; j < 448; j += 256) {
            const int r = j / 28, c4 = j % 28;
            const float4 v = pg[(size_t)r*L4 + ch*28 + c4];
            float4 t;
            CVT_TF32(t.x, v.x); CVT_TF32(t.y, v.y);
            CVT_TF32(t.z, v.z); CVT_TF32(t.w, v.w);
            *reinterpret_cast<float4*>(&p_s[r*FP + c4*4]) = t;
        }
        __syncthreads();

        #pragma unroll
        for (int kk = 0; kk < 14; ++kk) {
            const int lk = kk*8;
            const unsigned a0 = __float_as_uint(p_s[ gid     *FP + lk + tg    ]);
            const unsigned a1 = __float_as_uint(p_s[(gid + 8)*FP + lk + tg    ]);
            const unsigned a2 = __float_as_uint(p_s[ gid     *FP + lk + tg + 4]);
            const unsigned a3 = __float_as_uint(p_s[(gid + 8)*FP + lk + tg + 4]);
            const unsigned b0 = __float_as_uint(lf_s[(warp*8 + gid)*FP + lk + tg    ]);
            const unsigned b1 = __float_as_uint(lf_s[(warp*8 + gid)*FP + lk + tg + 4]);
            mma_tf32(d0, d1, d2, d3, a0, a1, a2, a3, b0, b1);
        }
    }

    const float inv_lo = inv_s[gid], inv_hi = inv_s[gid + 8];
    const int c = cblk*64 + warp*8 + 2*tg;
    float* frow_lo = g_f + ((size_t)n*MM + gid    )*CC;
    float* frow_hi = g_f + ((size_t)n*MM + gid + 8)*CC;
    *reinterpret_cast<float2*>(frow_lo + c) = make_float2(d0*inv_lo, d1*inv_lo);
    *reinterpret_cast<float2*>(frow_hi + c) = make_float2(d2*inv_hi, d3*inv_hi);
}

// ---------------------------------------------------------------------------
// Kernel D: out[n,m,d] = sum_c f[n,m,c]*Wu[d,c] + bu[d] + x[n,m,d]
// ---------------------------------------------------------------------------
__global__ __launch_bounds__(128) void k_out(const float* __restrict__ x,
                                             const float* __restrict__ Wu,
                                             const float* __restrict__ bu,
                                             float* __restrict__ out) {
    const int n = blockIdx.y;
    const int d = blockIdx.x * 128 + threadIdx.x;

    __shared__ float f_s[MM*CC];
    for (int j = threadIdx.x; j < MM*CC; j += 128) f_s[j] = g_f[n*MM*CC + j];
    __syncthreads();

    const float4* fs4  = reinterpret_cast<const float4*>(f_s);
    const float4* wrow = reinterpret_cast<const float4*>(Wu + (size_t)d*CC);

    float acc[MM];
    #pragma unroll
    for (int m = 0; m < MM; ++m) acc[m] = 0.f;

    #pragma unroll 2
    for (int c4 = 0; c4 < CC/4; ++c4) {
        const float4 w = wrow[c4];
        #pragma unroll
        for (int m = 0; m < MM; ++m) {
            const float4 fv = fs4[m*(CC/4) + c4];
            acc[m] += w.x*fv.x + w.y*fv.y + w.z*fv.z + w.w*fv.w;
        }
    }

    const float b = bu[d];
    #pragma unroll
    for (int m = 0; m < MM; ++m) {
        const int idx = n*MM*DD + m*DD + d;
        out[idx] = acc[m] + b + x[idx];
    }
}

// ---------------------------------------------------------------------------
extern "C" void kernel_launch(void* const* d_in, const int* in_sizes, int n_in,
                              void* d_out, int out_size) {
    const float* lf = (const float*)d_in[0];   // [64,384,56,56]
    const float* x  = (const float*)d_in[1];   // [64,16,384]
    const float* Wq = (const float*)d_in[2];   // [384,384]
    const float* bq = (const float*)d_in[3];   // [384]
    const float* Wu = (const float*)d_in[4];   // [384,384]
    const float* bu = (const float*)d_in[5];   // [384]
    float* out = (float*)d_out;                // [64,16,384]

    const int smem_scores = (16*QP + 32*LFP + 7*16) * (int)sizeof(float); // ~55 KB
    static int attr_done = 0;
    if (!attr_done) {
        cudaFuncSetAttribute(k_scores, cudaFuncAttributeMaxDynamicSharedMemorySize,
                             smem_scores);
        attr_done = 1;
    }

    k_q     <<<dim3(3,   64), 128>>>(x, Wq, bq);
    k_scores<<<dim3(NLB, 64), 224, smem_scores>>>(lf);
    k_fusion<<<dim3(6,   64), 256>>>(lf);
    k_out   <<<dim3(3,   64), 128>>>(x, Wu, bu, out);
}